// round 13
// baseline (speedup 1.0000x reference)
#include <cuda_runtime.h>
#include <cuda_fp16.h>
#include <cstdint>
#include <cstddef>

// ---- problem shapes ----
#define MM 8192
#define NN 11008
#define KK 4096
#define GG 32

// ---- GEMM tiling: 128x128 CTA, 4 warps of 64x64, BK=64 two-stage, 3 CTAs/SM ----
#define BM 128
#define BN 128
#define KP 64                       // stages of BK=64
#define THREADS 128

#define NB (NN / BN)                // 86
#define MB (MM / BM)                // 64
#define NTILES (MB * NB)            // 5504

#define A_HALVES 4096               // per (mb,kt32): 8 KB
#define A_KT_BYTES (A_HALVES * 2)
#define B_HALVES 4096               // per (nb,kt32): 8 KB  (BN=128: 16 nt-tiles x 256B x 2 kt2)
#define B_KT_BYTES (B_HALVES * 2)

// stage: [A kt0 8K][A kt1 8K][B kt0 8K][B kt1 8K] = 32 KB
#define STAGE_A_BYTES (2 * A_KT_BYTES)                 // 16384
#define STAGE_BYTES   (STAGE_A_BYTES + 2 * B_KT_BYTES) // 32768
#define SMEM_TOTAL    (2 * STAGE_BYTES)                // 65536 -> 3 CTAs/SM

#define XTILES (MB * 128 * 2 * 8)   // 131072
#define WTILES (NB * 128 * 2 * 16)  // 352256

// ---- scratch ----
__device__ __align__(256) __half g_Xa[(size_t)MM * KK];
__device__ __align__(256) __half g_Wb[(size_t)NN * KK];

// ---------------- helpers ----------------
__device__ __forceinline__ void cp16(uint32_t s, const void* g) {
    asm volatile("cp.async.cg.shared.global [%0], [%1], 16;" :: "r"(s), "l"(g));
}
__device__ __forceinline__ uint32_t smem_u32(const void* p) {
    uint32_t a;
    asm("{ .reg .u64 t; cvta.to.shared.u64 t, %1; cvt.u32.u64 %0, t; }"
        : "=r"(a) : "l"(p));
    return a;
}
__device__ __forceinline__ void cp_commit() {
    asm volatile("cp.async.commit_group;" ::: "memory");
}
__device__ __forceinline__ void cp_wait0() {
    asm volatile("cp.async.wait_group 0;" ::: "memory");
}
__device__ __forceinline__ void mma_f16(float* c, const uint32_t* a, const uint32_t* b) {
    asm volatile(
        "mma.sync.aligned.m16n8k16.row.col.f32.f16.f16.f32 "
        "{%0,%1,%2,%3}, {%4,%5,%6,%7}, {%8,%9}, {%0,%1,%2,%3};\n"
        : "+f"(c[0]), "+f"(c[1]), "+f"(c[2]), "+f"(c[3])
        : "r"(a[0]), "r"(a[1]), "r"(a[2]), "r"(a[3]),
          "r"(b[0]), "r"(b[1]));
}
__device__ __forceinline__ uint32_t pack2(float x, float y) {
    __half2 h = __floats2half2_rn(x, y);
    return *reinterpret_cast<uint32_t*>(&h);
}

// ---------------- merged prepass (X tiles, then W tiles; unroll-2) ----------------
__global__ void prep_all(const float* __restrict__ X, const float* __restrict__ SX,
                         const float* __restrict__ W, const float* __restrict__ WS,
                         const float* __restrict__ OFF) {
    const int lane = threadIdx.x & 31;
    const int gw = (blockIdx.x * blockDim.x + threadIdx.x) >> 5;
    const int nw = (gridDim.x * blockDim.x) >> 5;

    auto do_x = [&](int t) {
        const int mt  = t & 7;
        const int kt2 = (t >> 3) & 1;
        const int kt  = (t >> 4) & 127;
        const int mb  = t >> 11;
        const int r = mb * BM + mt * 16 + (lane >> 2);
        const int k = kt * 32 + kt2 * 16 + (lane & 3) * 2;
        const float s0 = __ldg(SX + r);
        const float s1 = __ldg(SX + r + 8);
        const float2 x00 = *reinterpret_cast<const float2*>(X + (size_t)r * KK + k);
        const float2 x10 = *reinterpret_cast<const float2*>(X + (size_t)(r + 8) * KK + k);
        const float2 x01 = *reinterpret_cast<const float2*>(X + (size_t)r * KK + k + 8);
        const float2 x11 = *reinterpret_cast<const float2*>(X + (size_t)(r + 8) * KK + k + 8);
        uint4 v;
        v.x = pack2(x00.x * s0, x00.y * s0);
        v.y = pack2(x10.x * s1, x10.y * s1);
        v.z = pack2(x01.x * s0, x01.y * s0);
        v.w = pack2(x11.x * s1, x11.y * s1);
        *reinterpret_cast<uint4*>(g_Xa + (size_t)t * 256 + lane * 8) = v;
    };

    // u = ((nb*128 + kt)*2 + kt2)*16 + nt ; 8x16 tile; lane holds uint2 at u*128 + lane*4
    auto do_w = [&](int u) {
        const int nt  = u & 15;
        const int kt2 = (u >> 4) & 1;
        const int kt  = (u >> 5) & 127;
        const int nb  = u >> 12;
        const int n = nb * BN + nt * 8 + (lane >> 2);
        const int k = kt * 32 + kt2 * 16 + (lane & 3) * 2;
        const int g = kt >> 2;
        const float ws  = __ldg(WS + (size_t)n * GG + g);
        const float off = __ldg(OFF + (size_t)n * GG + g);
        const float2 w0 = *reinterpret_cast<const float2*>(W + (size_t)n * KK + k);
        const float2 w1 = *reinterpret_cast<const float2*>(W + (size_t)n * KK + k + 8);
        uint2 v;
        v.x = pack2((w0.x - off) * ws, (w0.y - off) * ws);
        v.y = pack2((w1.x - off) * ws, (w1.y - off) * ws);
        *reinterpret_cast<uint2*>(g_Wb + (size_t)u * 128 + lane * 4) = v;
    };

    const int total = XTILES + WTILES;
    int t = gw * 2;
    const int stride = nw * 2;
    for (; t + 1 < total; t += stride) {
        if (t < XTILES) do_x(t); else do_w(t - XTILES);
        if (t + 1 < XTILES) do_x(t + 1); else do_w(t + 1 - XTILES);
    }
    if (t < total) {
        if (t < XTILES) do_x(t); else do_w(t - XTILES);
    }
}

// ---------------- GEMM: 4 warps of 64x64, BK=64 two-stage, 3 CTAs/SM ----------------
__global__ __launch_bounds__(THREADS, 3)
void gemm_frag(float* __restrict__ OUT) {
    extern __shared__ char smem[];
    const uint32_t sbase = smem_u32(smem);

    const int tid = threadIdx.x;
    const int wid = tid >> 5;       // 0..3
    const int lane = tid & 31;
    const int wm = wid >> 1;        // 0..1
    const int wn = wid & 1;         // 0..1

    // CTA swizzle: groups of 8 mb per nb sweep.
    const int bid = blockIdx.x;
    const int grp = bid / (8 * NB);
    const int rem = bid - grp * (8 * NB);
    const int mb = grp * 8 + (rem & 7);
    const int nb = rem >> 3;

    const __half* Ag = g_Xa + (size_t)mb * 128 * A_HALVES;
    const __half* Bg = g_Wb + (size_t)nb * 128 * B_HALVES;

    float acc[4][8][4];
    #pragma unroll
    for (int i = 0; i < 4; i++)
        #pragma unroll
        for (int j = 0; j < 8; j++)
            #pragma unroll
            for (int c = 0; c < 4; c++) acc[i][j][c] = 0.f;

    // stage s holds kt32 pair {2t, 2t+1}
    auto load_stage = [&](int buf, int t) {
        const uint32_t st = sbase + buf * STAGE_BYTES;
        #pragma unroll
        for (int h = 0; h < 2; h++) {
            const char* a = (const char*)(Ag + (size_t)(2 * t + h) * A_HALVES) + tid * 64;
            const uint32_t sa = st + h * A_KT_BYTES + tid * 64;
            #pragma unroll
            for (int j = 0; j < 4; j++) cp16(sa + j * 16, a + j * 16);
            const char* b = (const char*)(Bg + (size_t)(2 * t + h) * B_HALVES) + tid * 64;
            const uint32_t sb2 = st + STAGE_A_BYTES + h * B_KT_BYTES + tid * 64;
            #pragma unroll
            for (int j = 0; j < 4; j++) cp16(sb2 + j * 16, b + j * 16);
        }
        cp_commit();
    };

    auto compute = [&](int buf) {
        const char* stg = smem + buf * STAGE_BYTES;
        #pragma unroll
        for (int h = 0; h < 2; h++) {
            const char* As = stg + h * A_KT_BYTES;
            const char* Bs = stg + STAGE_A_BYTES + h * B_KT_BYTES;
            #pragma unroll
            for (int kt2 = 0; kt2 < 2; kt2++) {
                uint4 af[4];
                #pragma unroll
                for (int mi = 0; mi < 4; mi++) {
                    const int mt = wm * 4 + mi;
                    af[mi] = *reinterpret_cast<const uint4*>(
                        As + (kt2 * 8 + mt) * 512 + lane * 16);
                }
                uint2 bf[8];
                #pragma unroll
                for (int ni = 0; ni < 8; ni++) {
                    const int nt = wn * 8 + ni;
                    bf[ni] = *reinterpret_cast<const uint2*>(
                        Bs + (kt2 * 16 + nt) * 256 + lane * 8);
                }
                #pragma unroll
                for (int mi = 0; mi < 4; mi++)
                    #pragma unroll
                    for (int ni = 0; ni < 8; ni++)
                        mma_f16(acc[mi][ni],
                                reinterpret_cast<const uint32_t*>(&af[mi]),
                                reinterpret_cast<const uint32_t*>(&bf[ni]));
            }
        }
    };

    // pipeline: wait0 -> barrier -> prefetch next -> compute current
    load_stage(0, 0);
    #pragma unroll 1
    for (int t = 0; t < KP; t++) {
        cp_wait0();                 // copies for stage t landed
        __syncthreads();            // visible to all; compute t-1 done
        if (t + 1 < KP) load_stage((t + 1) & 1, t + 1);
        compute(t & 1);
    }

    // epilogue
    const int m0 = mb * BM + wm * 64;
    const int n0 = nb * BN + wn * 64;
    #pragma unroll
    for (int mi = 0; mi < 4; mi++) {
        const int row = m0 + mi * 16 + (lane >> 2);
        #pragma unroll
        for (int ni = 0; ni < 8; ni++) {
            const int col = n0 + ni * 8 + (lane & 3) * 2;
            float2 v0, v1;
            v0.x = acc[mi][ni][0]; v0.y = acc[mi][ni][1];
            v1.x = acc[mi][ni][2]; v1.y = acc[mi][ni][3];
            *reinterpret_cast<float2*>(OUT + (size_t)row * NN + col)       = v0;
            *reinterpret_cast<float2*>(OUT + (size_t)(row + 8) * NN + col) = v1;
        }
    }
}

// ---------------- launch ----------------
extern "C" void kernel_launch(void* const* d_in, const int* in_sizes, int n_in,
                              void* d_out, int out_size) {
    const float* X   = (const float*)d_in[0];
    const float* SX  = (const float*)d_in[1];
    const float* W   = (const float*)d_in[2];
    const float* WS  = (const float*)d_in[3];
    const float* OFF = (const float*)d_in[4];
    float* OUT = (float*)d_out;

    cudaFuncSetAttribute(gemm_frag,
                         cudaFuncAttributeMaxDynamicSharedMemorySize, SMEM_TOTAL);

    prep_all<<<2048, 256>>>(X, SX, W, WS, OFF);

    gemm_frag<<<NTILES, THREADS, SMEM_TOTAL>>>(OUT);
}

// round 14
// speedup vs baseline: 1.6378x; 1.6378x over previous
#include <cuda_runtime.h>
#include <cuda_fp16.h>
#include <cstdint>
#include <cstddef>

// ---- problem shapes ----
#define MM 8192
#define NN 11008
#define KK 4096
#define GG 32

// ---- GEMM: 128x256 CTA, 16 warps of 64x32, BK=64 four-stage, persistent ----
#define BM 128
#define BN 256
#define KP 64                       // 64 stages of BK=64 per tile
#define THREADS 512

#define NB (NN / BN)                // 43
#define MB (MM / BM)                // 64
#define NTILES (MB * NB)            // 2752
#define GRID 148

#define A_HALVES 4096               // per (mb,kt32): 8 KB
#define A_KT_BYTES (A_HALVES * 2)
#define B_HALVES 8192               // per (nb,kt32): 16 KB
#define B_KT_BYTES (B_HALVES * 2)

// stage: [A kt0 8K][A kt1 8K][B kt0 16K][B kt1 16K] = 48 KB
#define STAGE_A_BYTES (2 * A_KT_BYTES)                 // 16384
#define STAGE_BYTES   (STAGE_A_BYTES + 2 * B_KT_BYTES) // 49152
#define SMEM_TOTAL    (4 * STAGE_BYTES)                // 196608

#define XTILES (MB * 128 * 2 * 8)   // 131072
#define WTILES (NB * 128 * 2 * 32)  // 352256

// ---- scratch ----
__device__ __align__(256) __half g_Xa[(size_t)MM * KK];
__device__ __align__(256) __half g_Wb[(size_t)NN * KK];

// ---------------- helpers ----------------
__device__ __forceinline__ void cp16(uint32_t s, const void* g) {
    asm volatile("cp.async.cg.shared.global [%0], [%1], 16;" :: "r"(s), "l"(g));
}
__device__ __forceinline__ uint32_t smem_u32(const void* p) {
    uint32_t a;
    asm("{ .reg .u64 t; cvta.to.shared.u64 t, %1; cvt.u32.u64 %0, t; }"
        : "=r"(a) : "l"(p));
    return a;
}
__device__ __forceinline__ void cp_commit() {
    asm volatile("cp.async.commit_group;" ::: "memory");
}
__device__ __forceinline__ void cp_wait2() {
    asm volatile("cp.async.wait_group 2;" ::: "memory");
}
__device__ __forceinline__ void mma_f16(float* c, const uint32_t* a, const uint32_t* b) {
    asm volatile(
        "mma.sync.aligned.m16n8k16.row.col.f32.f16.f16.f32 "
        "{%0,%1,%2,%3}, {%4,%5,%6,%7}, {%8,%9}, {%0,%1,%2,%3};\n"
        : "+f"(c[0]), "+f"(c[1]), "+f"(c[2]), "+f"(c[3])
        : "r"(a[0]), "r"(a[1]), "r"(a[2]), "r"(a[3]),
          "r"(b[0]), "r"(b[1]));
}
__device__ __forceinline__ uint32_t pack2(float x, float y) {
    __half2 h = __floats2half2_rn(x, y);
    return *reinterpret_cast<uint32_t*>(&h);
}

// ---------------- merged prepass (X tiles, then W tiles; unroll-2) ----------------
__global__ void prep_all(const float* __restrict__ X, const float* __restrict__ SX,
                         const float* __restrict__ W, const float* __restrict__ WS,
                         const float* __restrict__ OFF) {
    const int lane = threadIdx.x & 31;
    const int gw = (blockIdx.x * blockDim.x + threadIdx.x) >> 5;
    const int nw = (gridDim.x * blockDim.x) >> 5;

    auto do_x = [&](int t) {
        const int mt  = t & 7;
        const int kt2 = (t >> 3) & 1;
        const int kt  = (t >> 4) & 127;
        const int mb  = t >> 11;
        const int r = mb * BM + mt * 16 + (lane >> 2);
        const int k = kt * 32 + kt2 * 16 + (lane & 3) * 2;
        const float s0 = __ldg(SX + r);
        const float s1 = __ldg(SX + r + 8);
        const float2 x00 = *reinterpret_cast<const float2*>(X + (size_t)r * KK + k);
        const float2 x10 = *reinterpret_cast<const float2*>(X + (size_t)(r + 8) * KK + k);
        const float2 x01 = *reinterpret_cast<const float2*>(X + (size_t)r * KK + k + 8);
        const float2 x11 = *reinterpret_cast<const float2*>(X + (size_t)(r + 8) * KK + k + 8);
        uint4 v;
        v.x = pack2(x00.x * s0, x00.y * s0);
        v.y = pack2(x10.x * s1, x10.y * s1);
        v.z = pack2(x01.x * s0, x01.y * s0);
        v.w = pack2(x11.x * s1, x11.y * s1);
        *reinterpret_cast<uint4*>(g_Xa + (size_t)t * 256 + lane * 8) = v;
    };

    auto do_w = [&](int u) {
        const int nt  = u & 31;
        const int kt2 = (u >> 5) & 1;
        const int kt  = (u >> 6) & 127;
        const int nb  = u >> 13;
        const int n = nb * BN + nt * 8 + (lane >> 2);
        const int k = kt * 32 + kt2 * 16 + (lane & 3) * 2;
        const int g = kt >> 2;
        const float ws  = __ldg(WS + (size_t)n * GG + g);
        const float off = __ldg(OFF + (size_t)n * GG + g);
        const float2 w0 = *reinterpret_cast<const float2*>(W + (size_t)n * KK + k);
        const float2 w1 = *reinterpret_cast<const float2*>(W + (size_t)n * KK + k + 8);
        uint2 v;
        v.x = pack2((w0.x - off) * ws, (w0.y - off) * ws);
        v.y = pack2((w1.x - off) * ws, (w1.y - off) * ws);
        *reinterpret_cast<uint2*>(g_Wb + (size_t)u * 128 + lane * 4) = v;
    };

    const int total = XTILES + WTILES;
    int t = gw * 2;
    const int stride = nw * 2;
    for (; t + 1 < total; t += stride) {
        if (t < XTILES) do_x(t); else do_w(t - XTILES);
        if (t + 1 < XTILES) do_x(t + 1); else do_w(t + 1 - XTILES);
    }
    if (t < total) {
        if (t < XTILES) do_x(t); else do_w(t - XTILES);
    }
}

// ---------------- persistent GEMM: continuous 4-stage stream across tiles ----------
__global__ __launch_bounds__(THREADS, 1)
void gemm_persist(float* __restrict__ OUT) {
    extern __shared__ char smem[];
    const uint32_t sbase = smem_u32(smem);

    const int tid = threadIdx.x;
    const int wid = tid >> 5;       // 0..15
    const int lane = tid & 31;
    const int wm = wid >> 3;        // 0..1
    const int wn = wid & 7;         // 0..7

    // stage "lt" of tile "tile": kt32 pair {2*lt, 2*lt+1}; empty commit past end.
    auto load_stage = [&](int buf, int tile, int lt) {
        if (tile < NTILES) {
            const int grp = tile / (8 * NB);
            const int rem = tile - grp * (8 * NB);
            const int mb = grp * 8 + (rem & 7);
            const int nb = rem >> 3;
            const __half* Ag = g_Xa + (size_t)mb * 128 * A_HALVES;
            const __half* Bg = g_Wb + (size_t)nb * 128 * B_HALVES;
            const uint32_t st = sbase + buf * STAGE_BYTES;
            #pragma unroll
            for (int h = 0; h < 2; h++) {
                const char* a = (const char*)(Ag + (size_t)(2 * lt + h) * A_HALVES) + tid * 16;
                cp16(st + h * A_KT_BYTES + tid * 16, a);
                const char* b = (const char*)(Bg + (size_t)(2 * lt + h) * B_HALVES) + tid * 32;
                const uint32_t sb2 = st + STAGE_A_BYTES + h * B_KT_BYTES + tid * 32;
                cp16(sb2, b);
                cp16(sb2 + 16, b + 16);
            }
        }
        cp_commit();                 // always commit: keeps wait_group depth uniform
    };

    float acc[4][4][4];

    auto compute = [&](int buf) {
        const char* stg = smem + buf * STAGE_BYTES;
        #pragma unroll
        for (int h = 0; h < 2; h++) {
            const char* As = stg + h * A_KT_BYTES;
            const char* Bs = stg + STAGE_A_BYTES + h * B_KT_BYTES;
            #pragma unroll
            for (int kt2 = 0; kt2 < 2; kt2++) {
                uint4 af[4];
                #pragma unroll
                for (int mi = 0; mi < 4; mi++) {
                    const int mt = wm * 4 + mi;
                    af[mi] = *reinterpret_cast<const uint4*>(
                        As + (kt2 * 8 + mt) * 512 + lane * 16);
                }
                uint2 bf[4];
                #pragma unroll
                for (int ni = 0; ni < 4; ni++) {
                    const int nt = wn * 4 + ni;
                    bf[ni] = *reinterpret_cast<const uint2*>(
                        Bs + (kt2 * 32 + nt) * 256 + lane * 8);
                }
                #pragma unroll
                for (int mi = 0; mi < 4; mi++)
                    #pragma unroll
                    for (int ni = 0; ni < 4; ni++)
                        mma_f16(acc[mi][ni],
                                reinterpret_cast<const uint32_t*>(&af[mi]),
                                reinterpret_cast<const uint32_t*>(&bf[ni]));
            }
        }
    };

    int ctile = blockIdx.x;
    if (ctile >= NTILES) return;

    // load iterator runs 3 stages ahead of compute, continuously across tiles
    int ltile = ctile, lt = 0, lbuf = 0;
    #pragma unroll
    for (int i = 0; i < 3; i++) {
        load_stage(lbuf, ltile, lt);
        lbuf = (lbuf + 1) & 3;
        if (++lt == KP) { lt = 0; ltile += GRID; }
    }

    int cbuf = 0;
    while (true) {
        #pragma unroll
        for (int i = 0; i < 4; i++)
            #pragma unroll
            for (int j = 0; j < 4; j++)
                #pragma unroll
                for (int c = 0; c < 4; c++) acc[i][j][c] = 0.f;

        #pragma unroll 1
        for (int t = 0; t < KP; t++) {
            cp_wait2();              // group for current stage (3 back) complete
            __syncthreads();         // copies visible; buffer being reloaded is free
            load_stage(lbuf, ltile, lt);
            lbuf = (lbuf + 1) & 3;
            if (++lt == KP) { lt = 0; ltile += GRID; }
            compute(cbuf);
            cbuf = (cbuf + 1) & 3;
        }

        // epilogue (overlaps in-flight loads for the next tile)
        {
            const int grp = ctile / (8 * NB);
            const int rem = ctile - grp * (8 * NB);
            const int mb = grp * 8 + (rem & 7);
            const int nb = rem >> 3;
            const int m0 = mb * BM + wm * 64;
            const int n0 = nb * BN + wn * 32;
            #pragma unroll
            for (int mi = 0; mi < 4; mi++) {
                const int row = m0 + mi * 16 + (lane >> 2);
                #pragma unroll
                for (int ni = 0; ni < 4; ni++) {
                    const int col = n0 + ni * 8 + (lane & 3) * 2;
                    float2 v0, v1;
                    v0.x = acc[mi][ni][0]; v0.y = acc[mi][ni][1];
                    v1.x = acc[mi][ni][2]; v1.y = acc[mi][ni][3];
                    *reinterpret_cast<float2*>(OUT + (size_t)row * NN + col)       = v0;
                    *reinterpret_cast<float2*>(OUT + (size_t)(row + 8) * NN + col) = v1;
                }
            }
        }

        ctile += GRID;
        if (ctile >= NTILES) break;
    }
}

// ---------------- launch ----------------
extern "C" void kernel_launch(void* const* d_in, const int* in_sizes, int n_in,
                              void* d_out, int out_size) {
    const float* X   = (const float*)d_in[0];
    const float* SX  = (const float*)d_in[1];
    const float* W   = (const float*)d_in[2];
    const float* WS  = (const float*)d_in[3];
    const float* OFF = (const float*)d_in[4];
    float* OUT = (float*)d_out;

    cudaFuncSetAttribute(gemm_persist,
                         cudaFuncAttributeMaxDynamicSharedMemorySize, SMEM_TOTAL);

    prep_all<<<2048, 256>>>(X, SX, W, WS, OFF);

    gemm_persist<<<GRID, THREADS, SMEM_TOTAL>>>(OUT);
}